// round 1
// baseline (speedup 1.0000x reference)
#include <cuda_runtime.h>
#include <cuda_bf16.h>

// DPLoss: masked per-row MSE of (pred - log(alignment)) over first len[i]
// positions, divided by len[i], averaged over B rows.
// B=4096, T=2048, fp32. HBM-bound (~67 MB traffic).

#define B_ROWS 4096
#define T_COLS 2048
#define T_VEC4 (T_COLS / 4)   // 512 float4 per row
#define NTHREADS 256

__global__ void dploss_zero(float* out) {
    *out = 0.0f;
}

__global__ __launch_bounds__(NTHREADS) void dploss_kernel(
    const float4* __restrict__ pred,
    const float4* __restrict__ align,
    const int* __restrict__ lens,
    float* __restrict__ out)
{
    const int row = blockIdx.x;
    const int len = lens[row];
    const float inv_len = 1.0f / (float)len;

    const float4* __restrict__ p = pred  + (size_t)row * T_VEC4;
    const float4* __restrict__ a = align + (size_t)row * T_VEC4;

    float s = 0.0f;

    #pragma unroll
    for (int it = 0; it < T_VEC4 / NTHREADS; ++it) {
        const int i = it * NTHREADS + threadIdx.x;   // vec4 index within row
        const int j = i * 4;                          // element index
        float4 pv = p[i];
        float4 av = a[i];
        float d0 = pv.x - __logf(av.x);
        float d1 = pv.y - __logf(av.y);
        float d2 = pv.z - __logf(av.z);
        float d3 = pv.w - __logf(av.w);
        if (j + 0 < len) s += d0 * d0;
        if (j + 1 < len) s += d1 * d1;
        if (j + 2 < len) s += d2 * d2;
        if (j + 3 < len) s += d3 * d3;
    }

    // warp reduction
    #pragma unroll
    for (int off = 16; off > 0; off >>= 1)
        s += __shfl_down_sync(0xFFFFFFFFu, s, off);

    // block reduction across 8 warps
    __shared__ float warp_sums[NTHREADS / 32];
    const int wid = threadIdx.x >> 5;
    const int lid = threadIdx.x & 31;
    if (lid == 0) warp_sums[wid] = s;
    __syncthreads();

    if (wid == 0) {
        float v = (lid < NTHREADS / 32) ? warp_sums[lid] : 0.0f;
        #pragma unroll
        for (int off = 4; off > 0; off >>= 1)
            v += __shfl_down_sync(0xFFFFFFFFu, v, off);
        if (lid == 0)
            atomicAdd(out, v * inv_len * (1.0f / (float)B_ROWS));
    }
}

extern "C" void kernel_launch(void* const* d_in, const int* in_sizes, int n_in,
                              void* d_out, int out_size)
{
    const float4* pred  = (const float4*)d_in[0];
    const float4* align = (const float4*)d_in[1];
    const int*    lens  = (const int*)d_in[2];
    float* out = (float*)d_out;

    dploss_zero<<<1, 1>>>(out);
    dploss_kernel<<<B_ROWS, NTHREADS>>>(pred, align, lens, out);
}